// round 2
// baseline (speedup 1.0000x reference)
#include <cuda_runtime.h>
#include <math.h>

#define BB 2
#define CC 64
#define HH 128
#define WW 128
#define OH 256
#define OW 256
#define HID 128

// scratch (allocation-free rule: __device__ globals)
__device__ float g_P[BB*HH*WW*HID];   // conv output, [b][y][x][oc], 16 MB
__device__ float g_cm[4*HID];         // per-parity (wk1_m @ m_emb + bk1)

__device__ __forceinline__ float gelu_exact(float x){
    return 0.5f * x * (1.0f + erff(x * 0.70710678118654752f));
}
__device__ __forceinline__ int refl(int i){
    if (i < 0) i = -i;
    if (i >= HH) i = 2*HH - 2 - i;
    return i;
}

// ---------------- Kernel A: 4 parity meta-embeddings -> c_m table -------------
__global__ void kernelA(const float* __restrict__ w1m, const float* __restrict__ b1m,
                        const float* __restrict__ w2m, const float* __restrict__ b2m,
                        const float* __restrict__ wk1, const float* __restrict__ bk1)
{
    __shared__ float enc[85], h1[64], memb[64];
    const int t = threadIdx.x;
    const float PI = 3.14159265358979323846f;
    for (int p = 0; p < 4; p++){
        float du = (p & 1) ? -0.25f : 0.25f;
        float dv = (p & 2) ? -0.25f : 0.25f;
        if (t < 85){
            int c = t / 17, r = t % 17;
            float mv = (c==0) ? 2.0f : ((c==1) ? du : ((c==2) ? dv : ((c==3) ? 0.5f : 0.3f)));
            float val;
            if (r == 0)      val = mv;
            else if (r <= 8) val = sinf(mv * ((float)(1 << (r-1)) * PI));
            else             val = cosf(mv * ((float)(1 << (r-9)) * PI));
            enc[t] = val;
        }
        __syncthreads();
        if (t < 64){
            float a = b1m[t];
            for (int i = 0; i < 85; i++) a += w1m[t*85 + i] * enc[i];
            h1[t] = gelu_exact(a);
        }
        __syncthreads();
        if (t < 64){
            float a = b2m[t];
            for (int i = 0; i < 64; i++) a += w2m[t*64 + i] * h1[i];
            memb[t] = a;
        }
        __syncthreads();
        {
            float a = bk1[t];
            for (int i = 0; i < 64; i++) a += wk1[t*640 + 576 + i] * memb[i];
            g_cm[p*128 + t] = a;
        }
        __syncthreads();
    }
}

// ---------------- Kernel B: 3x3 conv 64->128, reflect pad ---------------------
// grid (4 oc-groups, 64 tiles, 2 batch), block 256.
__global__ void __launch_bounds__(256) kernelB(const float* __restrict__ feat,
                                               const float* __restrict__ wk1)
{
    __shared__ float s_in[16*18*19];   // [ic][yy][xx] xx stride 19 (pad)
    __shared__ float s_w[32*144];      // [oc][ic*9+tap]

    const int t    = threadIdx.x;
    const int ocg  = blockIdx.x;           // 0..3  (32 oc each)
    const int tile = blockIdx.y;            // 0..63
    const int b    = blockIdx.z;
    const int y0 = (tile >> 3) * 16, x0 = (tile & 7) * 16;
    const int quad = t & 63;
    const int py  = quad >> 2;
    const int pxb = (quad & 3) * 4;
    const int oc0 = (t >> 6) * 8;

    float acc[8][4];
    #pragma unroll
    for (int j = 0; j < 8; j++)
        #pragma unroll
        for (int i = 0; i < 4; i++) acc[j][i] = 0.0f;

    for (int cc = 0; cc < 4; cc++){
        __syncthreads();
        for (int idx = t; idx < 32*144; idx += 256){
            int oc = idx / 144, r = idx % 144;
            s_w[idx] = wk1[(ocg*32 + oc)*640 + cc*144 + r];
        }
        for (int idx = t; idx < 16*324; idx += 256){
            int ic = idx / 324, r = idx % 324;
            int yy = r / 18, xx = r % 18;
            int ry = refl(y0 - 1 + yy), rx = refl(x0 - 1 + xx);
            s_in[ic*342 + yy*19 + xx] = feat[((b*CC + cc*16 + ic)*HH + ry)*WW + rx];
        }
        __syncthreads();

        for (int ic = 0; ic < 16; ic++){
            #pragma unroll
            for (int ky = 0; ky < 3; ky++){
                float v[6];
                #pragma unroll
                for (int u = 0; u < 6; u++)
                    v[u] = s_in[ic*342 + (py+ky)*19 + pxb + u];
                #pragma unroll
                for (int kx = 0; kx < 3; kx++){
                    #pragma unroll
                    for (int j = 0; j < 8; j++){
                        float wv = s_w[(oc0+j)*144 + ic*9 + ky*3 + kx];
                        acc[j][0] += wv * v[kx+0];
                        acc[j][1] += wv * v[kx+1];
                        acc[j][2] += wv * v[kx+2];
                        acc[j][3] += wv * v[kx+3];
                    }
                }
            }
        }
    }

    const int ocbase = ocg*32 + oc0;
    #pragma unroll
    for (int i = 0; i < 4; i++){
        int pix = (b*HH + y0 + py)*WW + (x0 + pxb + i);
        float4 v0 = make_float4(acc[0][i], acc[1][i], acc[2][i], acc[3][i]);
        float4 v1 = make_float4(acc[4][i], acc[5][i], acc[6][i], acc[7][i]);
        *(float4*)&g_P[pix*HID + ocbase    ] = v0;
        *(float4*)&g_P[pix*HID + ocbase + 4] = v1;
    }
}

// ---------------- Kernel C: per-query tail -----------------------------------
// block 256 = 8 warps, 1 warp per (b,q). grid = 131072/8 = 16384 blocks.
__global__ void __launch_bounds__(256) kernelC(const float* __restrict__ feat,
                                               const float* __restrict__ wk2,
                                               const float* __restrict__ bk2,
                                               const float* __restrict__ wr1,
                                               const float* __restrict__ br1,
                                               const float* __restrict__ wr2,
                                               const float* __restrict__ br2,
                                               float* __restrict__ out)
{
    // carve one shared buffer:
    // [0,4096)      wr1 paired-transpose: s[j*64+2i]=wr1[i*64+j] (i<32), s[j*64+2(i-32)+1]=wr1[i*64+j]
    // [4096,5248)   wk2 (9x128)
    // [5248,5760)   c_m (4x128)
    // [5760,6272)   f_q (8 warps x 64)
    // [6272,6336)   br1
    // [6336,6528)   wr2 (3x64)
    // [6528,6544)   bk2 (9)
    // [6544,6560)   br2 (3)
    __shared__ __align__(16) float s[6560];
    __shared__ int s_off[8*9];

    const int t = threadIdx.x;
    for (int idx = t; idx < 4096; idx += 256){
        int i = idx >> 6, j = idx & 63;
        int pos = j*64 + ((i < 32) ? 2*i : 2*(i-32) + 1);
        s[pos] = wr1[idx];
    }
    for (int idx = t; idx < 1152; idx += 256) s[4096 + idx] = wk2[idx];
    for (int idx = t; idx < 512;  idx += 256) s[5248 + idx] = g_cm[idx];
    if (t < 64)  s[6272 + t] = br1[t];
    if (t < 192) s[6336 + t] = wr2[t];
    if (t < 9)   s[6528 + t] = bk2[t];
    if (t < 3)   s[6544 + t] = br2[t];
    __syncthreads();

    const int w = t >> 5, lane = t & 31;
    const int wg = blockIdx.x * 8 + w;      // global (b,q) id
    const int b = wg >> 16;
    const int q = wg & 65535;
    const int y = q >> 8, x = q & 255;
    const int cy = max(0, (y - 1) >> 1);
    const int cx = max(0, (x - 1) >> 1);
    const int par = (y & 1) * 2 + (x & 1);

    // h = gelu(P[cell] + c_m[parity])  (4 channels per lane)
    const float4* P4 = (const float4*)g_P;
    const int cellbase = ((b*HH + cy)*WW + cx) * HID;
    float4 pv  = P4[(cellbase >> 2) + lane];
    float4 cmv = *(const float4*)&s[5248 + par*128 + lane*4];
    float h0 = gelu_exact(pv.x + cmv.x);
    float h1 = gelu_exact(pv.y + cmv.y);
    float h2 = gelu_exact(pv.z + cmv.z);
    float h3 = gelu_exact(pv.w + cmv.w);

    // logits[9] = bk2 + wk2 @ h  (warp reduction -> all lanes)
    float lg[9];
    #pragma unroll
    for (int k = 0; k < 9; k++){
        float4 wv = *(const float4*)&s[4096 + k*128 + lane*4];
        float pr = wv.x*h0 + wv.y*h1 + wv.z*h2 + wv.w*h3;
        #pragma unroll
        for (int off = 16; off; off >>= 1) pr += __shfl_xor_sync(0xffffffffu, pr, off);
        lg[k] = pr + s[6528 + k];
    }

    // softmax
    float mx = lg[0];
    #pragma unroll
    for (int k = 1; k < 9; k++) mx = fmaxf(mx, lg[k]);
    float wk[9], ssum = 0.0f;
    #pragma unroll
    for (int k = 0; k < 9; k++){ wk[k] = expf(lg[k] - mx); ssum += wk[k]; }
    float inv = 1.0f / ssum;
    #pragma unroll
    for (int k = 0; k < 9; k++) wk[k] *= inv;

    // per-query tap offsets
    if (lane < 9){
        int ky = lane / 3, kx = lane % 3;
        s_off[w*9 + lane] = refl(cy - 1 + ky)*WW + refl(cx - 1 + kx);
    }
    __syncwarp();

    // f_q[c] = sum_k wk[k] * flat[k*64 + c],  flat[i] = feat[b][i/9][tap i%9]
    float fq0 = 0.0f, fq1 = 0.0f;
    const int featb = b * CC * HH * WW;
    #pragma unroll
    for (int k = 0; k < 9; k++){
        {
            int i = k*64 + lane;
            int c = i / 9; int tap = i - 9*c;
            fq0 += wk[k] * feat[featb + c*16384 + s_off[w*9 + tap]];
        }
        {
            int i = k*64 + lane + 32;
            int c = i / 9; int tap = i - 9*c;
            fq1 += wk[k] * feat[featb + c*16384 + s_off[w*9 + tap]];
        }
    }
    s[5760 + w*64 + lane]      = fq0;
    s[5760 + w*64 + lane + 32] = fq1;
    __syncwarp();

    // t1 = gelu(wr1 @ f_q + br1), rows lane and lane+32
    float a0 = s[6272 + lane], a1 = s[6272 + lane + 32];
    #pragma unroll 8
    for (int j = 0; j < 64; j++){
        float fj = s[5760 + w*64 + j];
        float2 wv = *(const float2*)&s[j*64 + lane*2];
        a0 += wv.x * fj;
        a1 += wv.y * fj;
    }
    a0 = gelu_exact(a0);
    a1 = gelu_exact(a1);

    // out[r] = br2 + wr2 @ t1
    #pragma unroll
    for (int r = 0; r < 3; r++){
        float pr = s[6336 + r*64 + lane] * a0 + s[6336 + r*64 + lane + 32] * a1;
        #pragma unroll
        for (int off = 16; off; off >>= 1) pr += __shfl_xor_sync(0xffffffffu, pr, off);
        if (lane == 0) out[((b*3 + r)*OH + y)*OW + x] = pr + s[6544 + r];
    }
}

// ------------------------------------------------------------------------------
extern "C" void kernel_launch(void* const* d_in, const int* in_sizes, int n_in,
                              void* d_out, int out_size)
{
    const float* feat = (const float*)d_in[0];
    const float* w1m  = (const float*)d_in[1];
    const float* b1m  = (const float*)d_in[2];
    const float* w2m  = (const float*)d_in[3];
    const float* b2m  = (const float*)d_in[4];
    const float* wk1  = (const float*)d_in[5];
    const float* bk1  = (const float*)d_in[6];
    const float* wk2  = (const float*)d_in[7];
    const float* bk2  = (const float*)d_in[8];
    const float* wr1  = (const float*)d_in[9];
    const float* br1  = (const float*)d_in[10];
    const float* wr2  = (const float*)d_in[11];
    const float* br2  = (const float*)d_in[12];
    float* out = (float*)d_out;

    kernelA<<<1, 128>>>(w1m, b1m, w2m, b2m, wk1, bk1);
    dim3 gridB(4, 64, BB);
    kernelB<<<gridB, 256>>>(feat, wk1);
    kernelC<<<16384, 256>>>(feat, wk2, bk2, wr1, br1, wr2, br2, out);
}

// round 3
// speedup vs baseline: 1.8279x; 1.8279x over previous
#include <cuda_runtime.h>
#include <math.h>

#define BB 2
#define CC 64
#define HH 128
#define WW 128
#define OH 256
#define OW 256
#define HID 128

__device__ float g_P[BB*HH*WW*HID];   // conv output, [b][y][x][oc], 16 MB
__device__ float g_F[BB*HH*WW*CC];    // transposed feat, [b][y][x][c], 8 MB
__device__ float g_cm[4*HID];         // per-parity (wk1_m @ m_emb + bk1)

__device__ __forceinline__ float gelu_exact(float x){
    return 0.5f * x * (1.0f + erff(x * 0.70710678118654752f));
}
__device__ __forceinline__ int refl(int i){
    if (i < 0) i = -i;
    if (i >= HH) i = 2*HH - 2 - i;
    return i;
}
__device__ __forceinline__ unsigned long long pack2(float lo, float hi){
    unsigned long long r;
    asm("mov.b64 %0, {%1,%2};" : "=l"(r) : "f"(lo), "f"(hi));
    return r;
}
#define FMA2(acc, a, b) asm("fma.rn.f32x2 %0, %1, %2, %0;" : "+l"(acc) : "l"(a), "l"(b))

// ---------------- Kernel T: feat transpose (+ fused meta-embedding blocks) ----
// blocks [0,1024): transpose. blocks [1024,1028): one parity of kernelA each.
__global__ void __launch_bounds__(256) kernelT(const float* __restrict__ feat,
                        const float* __restrict__ w1m, const float* __restrict__ b1m,
                        const float* __restrict__ w2m, const float* __restrict__ b2m,
                        const float* __restrict__ wk1, const float* __restrict__ bk1)
{
    __shared__ float tile[64*33];
    const int t = threadIdx.x;
    const int bx = blockIdx.x;

    if (bx >= 1024){
        // ---- meta-embedding for parity p ----
        const int p = bx - 1024;
        float* enc  = tile;        // 85
        float* h1   = tile + 96;   // 64
        float* memb = tile + 160;  // 64
        const float PI = 3.14159265358979323846f;
        float du = (p & 1) ? -0.25f : 0.25f;
        float dv = (p & 2) ? -0.25f : 0.25f;
        if (t < 85){
            int c = t / 17, r = t % 17;
            float mv = (c==0) ? 2.0f : ((c==1) ? du : ((c==2) ? dv : ((c==3) ? 0.5f : 0.3f)));
            float val;
            if (r == 0)      val = mv;
            else if (r <= 8) val = sinf(mv * ((float)(1 << (r-1)) * PI));
            else             val = cosf(mv * ((float)(1 << (r-9)) * PI));
            enc[t] = val;
        }
        __syncthreads();
        if (t < 64){
            float a = b1m[t];
            #pragma unroll 5
            for (int i = 0; i < 85; i++) a += w1m[t*85 + i] * enc[i];
            h1[t] = gelu_exact(a);
        }
        __syncthreads();
        if (t < 64){
            float a = b2m[t];
            #pragma unroll 8
            for (int i = 0; i < 64; i++) a += w2m[t*64 + i] * h1[i];
            memb[t] = a;
        }
        __syncthreads();
        if (t < 128){
            float a = bk1[t];
            #pragma unroll 8
            for (int i = 0; i < 64; i++) a += wk1[t*640 + 576 + i] * memb[i];
            g_cm[p*128 + t] = a;
        }
        return;
    }

    // ---- transpose: one (b, y, 32-wide x tile) per block ----
    const int b  = bx >> 9;
    const int y  = (bx >> 2) & 127;
    const int x0 = (bx & 3) * 32;
    for (int idx = t; idx < 2048; idx += 256){
        int c = idx >> 5, xx = idx & 31;
        tile[c*33 + xx] = feat[((b*CC + c)*HH + y)*WW + x0 + xx];
    }
    __syncthreads();
    for (int idx = t; idx < 2048; idx += 256){
        int xx = idx >> 6, c = idx & 63;
        g_F[((b*HH + y)*WW + x0 + xx)*CC + c] = tile[c*33 + xx];
    }
}

// ---------------- Kernel B: 3x3 conv 64->128, reflect pad, f32x2 FMA ----------
// grid (4 oc-groups, 64 tiles, 2 batch), block 256.
__global__ void __launch_bounds__(256) kernelB(const float* __restrict__ feat,
                                               const float* __restrict__ wk1)
{
    __shared__ __align__(16) float s_in[16*18*19];   // [ic][yy][xx], xx stride 19
    __shared__ __align__(16) float s_w[144*34];      // [r=ic*9+tap][oc], stride 34

    const int t    = threadIdx.x;
    const int ocg  = blockIdx.x;            // 0..3  (32 oc each)
    const int tile = blockIdx.y;            // 0..63
    const int b    = blockIdx.z;
    const int y0 = (tile >> 3) * 16, x0 = (tile & 7) * 16;
    const int quad = t & 63;
    const int py  = quad >> 2;
    const int pxb = (quad & 3) * 4;
    const int oc0 = (t >> 6) * 8;           // local oc base (8 per thread)

    unsigned long long accp[4][4];          // [j2 ocpair][i pixel], f32x2
    #pragma unroll
    for (int j2 = 0; j2 < 4; j2++)
        #pragma unroll
        for (int i = 0; i < 4; i++) accp[j2][i] = 0ull;

    for (int cc = 0; cc < 4; cc++){
        __syncthreads();
        for (int idx = t; idx < 32*144; idx += 256){
            int oc = idx / 144, r = idx % 144;
            s_w[r*34 + oc] = wk1[(ocg*32 + oc)*640 + cc*144 + r];
        }
        for (int idx = t; idx < 16*324; idx += 256){
            int ic = idx / 324, r = idx % 324;
            int yy = r / 18, xx = r % 18;
            int ry = refl(y0 - 1 + yy), rx = refl(x0 - 1 + xx);
            s_in[ic*342 + yy*19 + xx] = feat[((b*CC + cc*16 + ic)*HH + ry)*WW + rx];
        }
        __syncthreads();

        for (int ic = 0; ic < 16; ic++){
            #pragma unroll
            for (int ky = 0; ky < 3; ky++){
                float v[6];
                #pragma unroll
                for (int u = 0; u < 6; u++)
                    v[u] = s_in[ic*342 + (py+ky)*19 + pxb + u];
                unsigned long long vs[6];
                #pragma unroll
                for (int u = 0; u < 6; u++) vs[u] = pack2(v[u], v[u]);
                #pragma unroll
                for (int kx = 0; kx < 3; kx++){
                    const int r = ic*9 + ky*3 + kx;
                    #pragma unroll
                    for (int j2 = 0; j2 < 4; j2++){
                        unsigned long long wp =
                            *(const unsigned long long*)&s_w[r*34 + oc0 + 2*j2];
                        FMA2(accp[j2][0], wp, vs[kx+0]);
                        FMA2(accp[j2][1], wp, vs[kx+1]);
                        FMA2(accp[j2][2], wp, vs[kx+2]);
                        FMA2(accp[j2][3], wp, vs[kx+3]);
                    }
                }
            }
        }
    }

    const int ocbase = ocg*32 + oc0;
    #pragma unroll
    for (int i = 0; i < 4; i++){
        int pix = (b*HH + y0 + py)*WW + (x0 + pxb + i);
        #pragma unroll
        for (int j2 = 0; j2 < 4; j2++){
            float lo, hi;
            asm("mov.b64 {%0,%1}, %2;" : "=f"(lo), "=f"(hi) : "l"(accp[j2][i]));
            *(float2*)&g_P[pix*HID + ocbase + 2*j2] = make_float2(lo, hi);
        }
    }
}

// ---------------- Kernel C: per-query tail (tile-based) -----------------------
// block 256 = 8 warps; warp w handles queries x = x0+w, y = y0..y0+3.
// grid (32, 64, 2).
__global__ void __launch_bounds__(256) kernelC(const float* __restrict__ wk2,
                                               const float* __restrict__ bk2,
                                               const float* __restrict__ wr1,
                                               const float* __restrict__ br1,
                                               const float* __restrict__ wr2,
                                               const float* __restrict__ br2,
                                               float* __restrict__ out)
{
    // [0,4096)    wr1 paired-transpose
    // [4096,5248) wk2 (9x128)
    // [5248,5760) c_m (4x128)
    // [5760,6272) f_q (8 warps x 64)
    // [6272,6336) br1
    // [6336,6528) wr2 (3x64)
    // [6528,6537) bk2 ; [6544,6547) br2
    __shared__ __align__(16) float s[6560];
    __shared__ __align__(16) float s_f[64*35];   // [c][pix], 5 rows x 7 cols

    const int t = threadIdx.x;
    const int x0 = blockIdx.x * 8;
    const int y0 = blockIdx.y * 4;
    const int b  = blockIdx.z;

    for (int idx = t; idx < 4096; idx += 256){
        int i = idx >> 6, j = idx & 63;
        int pos = j*64 + ((i < 32) ? 2*i : 2*(i-32) + 1);
        s[pos] = wr1[idx];
    }
    for (int idx = t; idx < 1152; idx += 256) s[4096 + idx] = wk2[idx];
    for (int idx = t; idx < 512;  idx += 256) s[5248 + idx] = g_cm[idx];
    if (t < 64)  s[6272 + t] = br1[t];
    if (t < 192) s[6336 + t] = wr2[t];
    if (t < 9)   s[6528 + t] = bk2[t];
    if (t < 3)   s[6544 + t] = br2[t];

    // tap window: rows refl(y0/2-2 + 0..4), cols refl(x0/2-2 + 0..6)
    const int rowbase = (y0 >> 1) - 2;
    const int colbase = (x0 >> 1) - 2;
    for (int idx = t; idx < 35*64; idx += 256){
        int pix = idx >> 6, c = idx & 63;
        int wr = pix / 7, wc = pix % 7;
        int gy = refl(rowbase + wr), gx = refl(colbase + wc);
        s_f[c*35 + pix] = g_F[((b*HH + gy)*WW + gx)*CC + c];
    }
    __syncthreads();

    const int w = t >> 5, lane = t & 31;
    const int x = x0 + w;
    const int cx = max(0, (x - 1) >> 1);
    const int coloff = cx + 1 - (x0 >> 1);      // window col of tap kx=0

    const float4* P4 = (const float4*)g_P;

    for (int qi = 0; qi < 4; qi++){
        const int y = y0 + qi;
        const int cy = max(0, (y - 1) >> 1);
        const int par = ((y & 1) << 1) | (x & 1);
        const int rowoff = cy + 1 - (y0 >> 1);  // window row of tap ky=0
        const int qbase = rowoff*7 + coloff;

        // h = gelu(P[cell] + c_m[parity])
        float4 pv  = P4[((b*HH + cy)*WW + cx)*(HID/4) + lane];
        float4 cmv = *(const float4*)&s[5248 + par*128 + lane*4];
        float h0 = gelu_exact(pv.x + cmv.x);
        float h1 = gelu_exact(pv.y + cmv.y);
        float h2 = gelu_exact(pv.z + cmv.z);
        float h3 = gelu_exact(pv.w + cmv.w);

        // logits[9]
        float lg[9];
        #pragma unroll
        for (int k = 0; k < 9; k++){
            float4 wv = *(const float4*)&s[4096 + k*128 + lane*4];
            float pr = wv.x*h0 + wv.y*h1 + wv.z*h2 + wv.w*h3;
            #pragma unroll
            for (int off = 16; off; off >>= 1) pr += __shfl_xor_sync(0xffffffffu, pr, off);
            lg[k] = pr + s[6528 + k];
        }

        // softmax
        float mx = lg[0];
        #pragma unroll
        for (int k = 1; k < 9; k++) mx = fmaxf(mx, lg[k]);
        float wk[9], ssum = 0.0f;
        #pragma unroll
        for (int k = 0; k < 9; k++){ wk[k] = expf(lg[k] - mx); ssum += wk[k]; }
        float inv = 1.0f / ssum;
        #pragma unroll
        for (int k = 0; k < 9; k++) wk[k] *= inv;

        // f_q[c] = sum_k wk[k] * flat[k*64+c], flat[i]=feat[ch=i/9][tap=i%9]
        float fq0 = 0.0f, fq1 = 0.0f;
        #pragma unroll
        for (int k = 0; k < 9; k++){
            {
                int i = k*64 + lane;
                int ch = i / 9; int tap = i - 9*ch;
                int tap7 = tap + (tap/3)*4;
                fq0 += wk[k] * s_f[ch*35 + qbase + tap7];
            }
            {
                int i = k*64 + lane + 32;
                int ch = i / 9; int tap = i - 9*ch;
                int tap7 = tap + (tap/3)*4;
                fq1 += wk[k] * s_f[ch*35 + qbase + tap7];
            }
        }
        s[5760 + w*64 + lane]      = fq0;
        s[5760 + w*64 + lane + 32] = fq1;
        __syncwarp();

        // t1 = gelu(wr1 @ f_q + br1)
        float a0 = s[6272 + lane], a1 = s[6272 + lane + 32];
        #pragma unroll 8
        for (int j = 0; j < 64; j++){
            float fj = s[5760 + w*64 + j];
            float2 wv = *(const float2*)&s[j*64 + lane*2];
            a0 += wv.x * fj;
            a1 += wv.y * fj;
        }
        a0 = gelu_exact(a0);
        a1 = gelu_exact(a1);

        // out[r] = br2 + wr2 @ t1
        #pragma unroll
        for (int r = 0; r < 3; r++){
            float pr = s[6336 + r*64 + lane] * a0 + s[6336 + r*64 + lane + 32] * a1;
            #pragma unroll
            for (int off = 16; off; off >>= 1) pr += __shfl_xor_sync(0xffffffffu, pr, off);
            if (lane == 0) out[((b*3 + r)*OH + y)*OW + x] = pr + s[6544 + r];
        }
        __syncwarp();
    }
}

// ------------------------------------------------------------------------------
extern "C" void kernel_launch(void* const* d_in, const int* in_sizes, int n_in,
                              void* d_out, int out_size)
{
    const float* feat = (const float*)d_in[0];
    const float* w1m  = (const float*)d_in[1];
    const float* b1m  = (const float*)d_in[2];
    const float* w2m  = (const float*)d_in[3];
    const float* b2m  = (const float*)d_in[4];
    const float* wk1  = (const float*)d_in[5];
    const float* bk1  = (const float*)d_in[6];
    const float* wk2  = (const float*)d_in[7];
    const float* bk2  = (const float*)d_in[8];
    const float* wr1  = (const float*)d_in[9];
    const float* br1  = (const float*)d_in[10];
    const float* wr2  = (const float*)d_in[11];
    const float* br2  = (const float*)d_in[12];
    float* out = (float*)d_out;

    kernelT<<<1028, 256>>>(feat, w1m, b1m, w2m, b2m, wk1, bk1);
    dim3 gridB(4, 64, BB);
    kernelB<<<gridB, 256>>>(feat, wk1);
    dim3 gridC(32, 64, BB);
    kernelC<<<gridC, 256>>>(wk2, bk2, wr1, br1, wr2, br2, out);
}

// round 4
// speedup vs baseline: 2.2158x; 1.2122x over previous
#include <cuda_runtime.h>
#include <math.h>

#define BB 2
#define CC 64
#define HH 128
#define WW 128
#define OH 256
#define OW 256
#define HID 128

typedef unsigned long long ull;

__device__ float g_P[BB*HH*WW*HID];   // conv output, [b][y][x][oc], 16 MB
__device__ float g_F[BB*HH*WW*CC];    // transposed feat, [b][y][x][c], 8 MB
__device__ float g_cm[4*HID];         // per-parity (wk1_m @ m_emb + bk1)

__device__ __forceinline__ float gelu_exact(float x){
    return 0.5f * x * (1.0f + erff(x * 0.70710678118654752f));
}
// fast erf-gelu: Abramowitz-Stegun 7.1.26, |err_erf| <= 1.5e-7
__device__ __forceinline__ float gelu_fast(float x){
    float z  = x * 0.70710678118654752f;
    float az = fabsf(z);
    float t  = __frcp_rn(1.0f + 0.3275911f * az);
    float poly = t*(0.254829592f + t*(-0.284496736f + t*(1.421413741f
               + t*(-1.453152027f + t*1.061405429f))));
    float e = __expf(-z*z);
    float erfv = copysignf(1.0f - poly*e, z);
    return 0.5f * x * (1.0f + erfv);
}
__device__ __forceinline__ int refl(int i){
    if (i < 0) i = -i;
    if (i >= HH) i = 2*HH - 2 - i;
    return i;
}
__device__ __forceinline__ ull pack2(float lo, float hi){
    ull r;
    asm("mov.b64 %0, {%1,%2};" : "=l"(r) : "f"(lo), "f"(hi));
    return r;
}
#define FMA2(acc, a, b) asm("fma.rn.f32x2 %0, %1, %2, %0;" : "+l"(acc) : "l"(a), "l"(b))
#define UNPACK2(lo, hi, p) asm("mov.b64 {%0,%1}, %2;" : "=f"(lo), "=f"(hi) : "l"(p))

// ---------------- Kernel T: feat transpose (+ fused meta-embedding blocks) ----
__global__ void __launch_bounds__(256) kernelT(const float* __restrict__ feat,
                        const float* __restrict__ w1m, const float* __restrict__ b1m,
                        const float* __restrict__ w2m, const float* __restrict__ b2m,
                        const float* __restrict__ wk1, const float* __restrict__ bk1)
{
    __shared__ float tile[64*33];
    const int t = threadIdx.x;
    const int bx = blockIdx.x;

    if (bx >= 1024){
        const int p = bx - 1024;
        float* enc  = tile;
        float* h1   = tile + 96;
        float* memb = tile + 160;
        const float PI = 3.14159265358979323846f;
        float du = (p & 1) ? -0.25f : 0.25f;
        float dv = (p & 2) ? -0.25f : 0.25f;
        if (t < 85){
            int c = t / 17, r = t % 17;
            float mv = (c==0) ? 2.0f : ((c==1) ? du : ((c==2) ? dv : ((c==3) ? 0.5f : 0.3f)));
            float val;
            if (r == 0)      val = mv;
            else if (r <= 8) val = sinf(mv * ((float)(1 << (r-1)) * PI));
            else             val = cosf(mv * ((float)(1 << (r-9)) * PI));
            enc[t] = val;
        }
        __syncthreads();
        if (t < 64){
            float a = b1m[t];
            #pragma unroll 5
            for (int i = 0; i < 85; i++) a += w1m[t*85 + i] * enc[i];
            h1[t] = gelu_exact(a);
        }
        __syncthreads();
        if (t < 64){
            float a = b2m[t];
            #pragma unroll 8
            for (int i = 0; i < 64; i++) a += w2m[t*64 + i] * h1[i];
            memb[t] = a;
        }
        __syncthreads();
        if (t < 128){
            float a = bk1[t];
            #pragma unroll 8
            for (int i = 0; i < 64; i++) a += wk1[t*640 + 576 + i] * memb[i];
            g_cm[p*128 + t] = a;
        }
        return;
    }

    const int b  = bx >> 9;
    const int y  = (bx >> 2) & 127;
    const int x0 = (bx & 3) * 32;
    for (int idx = t; idx < 2048; idx += 256){
        int c = idx >> 5, xx = idx & 31;
        tile[c*33 + xx] = feat[((b*CC + c)*HH + y)*WW + x0 + xx];
    }
    __syncthreads();
    for (int idx = t; idx < 2048; idx += 256){
        int xx = idx >> 6, c = idx & 63;
        g_F[((b*HH + y)*WW + x0 + xx)*CC + c] = tile[c*33 + xx];
    }
}

// ---------------- Kernel B: 3x3 conv 64->128, f32x2, 8px x 8oc per thread -----
// grid (2 ocg, 64 tiles, 2 b), block 256 = 8 warps (one oc-group per warp).
__global__ void __launch_bounds__(256) kernelB(const float* __restrict__ feat,
                                               const float* __restrict__ wk1)
{
    __shared__ __align__(16) float s_in[8*18*19];   // [ic][yy][xx], row stride 19
    __shared__ __align__(16) float s_w[72*64];      // [r=icl*9+tap][oc]

    const int t    = threadIdx.x;
    const int ocg  = blockIdx.x;            // 0..1 (64 oc each)
    const int tile = blockIdx.y;            // 0..63
    const int b    = blockIdx.z;
    const int y0 = (tile >> 3) * 16, x0 = (tile & 7) * 16;
    const int lane = t & 31;
    const int og   = t >> 5;                // warp id = oc group (8 oc)
    const int row  = lane >> 1;             // 0..15
    const int xh   = (lane & 1) * 8;        // 0 or 8
    const int oc0  = og * 8;

    ull accp[4][8];
    #pragma unroll
    for (int j2 = 0; j2 < 4; j2++)
        #pragma unroll
        for (int i = 0; i < 8; i++) accp[j2][i] = 0ull;

    for (int cc = 0; cc < 8; cc++){
        __syncthreads();
        for (int idx = t; idx < 72*64; idx += 256){
            int r = idx >> 6, oc = idx & 63;
            s_w[idx] = wk1[(ocg*64 + oc)*640 + cc*72 + r];
        }
        for (int idx = t; idx < 8*324; idx += 256){
            int ic = idx / 324, r2 = idx % 324;
            int yy = r2 / 18, xx = r2 % 18;
            int ry = refl(y0 - 1 + yy), rx = refl(x0 - 1 + xx);
            s_in[ic*342 + yy*19 + xx] = feat[((b*CC + cc*8 + ic)*HH + ry)*WW + rx];
        }
        __syncthreads();

        #pragma unroll 1
        for (int ic = 0; ic < 8; ic++){
            #pragma unroll
            for (int ky = 0; ky < 3; ky++){
                float v[10];
                #pragma unroll
                for (int u = 0; u < 10; u++)
                    v[u] = s_in[ic*342 + (row+ky)*19 + xh + u];
                ull vs[10];
                #pragma unroll
                for (int u = 0; u < 10; u++) vs[u] = pack2(v[u], v[u]);
                #pragma unroll
                for (int kx = 0; kx < 3; kx++){
                    const int r = ic*9 + ky*3 + kx;
                    ulonglong2 wA = *(const ulonglong2*)&s_w[r*64 + oc0];
                    ulonglong2 wB = *(const ulonglong2*)&s_w[r*64 + oc0 + 4];
                    #pragma unroll
                    for (int px = 0; px < 8; px++){
                        FMA2(accp[0][px], wA.x, vs[px+kx]);
                        FMA2(accp[1][px], wA.y, vs[px+kx]);
                        FMA2(accp[2][px], wB.x, vs[px+kx]);
                        FMA2(accp[3][px], wB.y, vs[px+kx]);
                    }
                }
            }
        }
    }

    const int ocbase = ocg*64 + oc0;
    #pragma unroll
    for (int px = 0; px < 8; px++){
        int pix = (b*HH + y0 + row)*WW + (x0 + xh + px);
        float o0,o1,o2,o3,o4,o5,o6,o7;
        UNPACK2(o0,o1, accp[0][px]);
        UNPACK2(o2,o3, accp[1][px]);
        UNPACK2(o4,o5, accp[2][px]);
        UNPACK2(o6,o7, accp[3][px]);
        *(float4*)&g_P[pix*HID + ocbase    ] = make_float4(o0,o1,o2,o3);
        *(float4*)&g_P[pix*HID + ocbase + 4] = make_float4(o4,o5,o6,o7);
    }
}

// ---------------- Kernel C: per-query tail (tile-based, batched MLP) ----------
// block 256 = 8 warps; warp w -> x = x0+w, queries y = y0..y0+3. grid (32,64,2).
#define SW1  0
#define SWK2 4224
#define SCM  5376
#define SFQ  5888
#define SBR1 7936
#define SWR2 8000
#define SBK2 8192
#define SBR2 8204
__global__ void __launch_bounds__(256) kernelC(const float* __restrict__ wk2,
                                               const float* __restrict__ bk2,
                                               const float* __restrict__ wr1,
                                               const float* __restrict__ br1,
                                               const float* __restrict__ wr2,
                                               const float* __restrict__ br2,
                                               float* __restrict__ out)
{
    __shared__ __align__(16) float s[8208];
    __shared__ __align__(16) float s_f[64*35];   // [c][pix], 5 rows x 7 cols

    const int t = threadIdx.x;
    const int x0 = blockIdx.x * 8;
    const int y0 = blockIdx.y * 4;
    const int b  = blockIdx.z;

    for (int idx = t; idx < 4096; idx += 256){
        int o = idx >> 6, j = idx & 63;
        s[SW1 + o*66 + j] = wr1[idx];
    }
    for (int idx = t; idx < 1152; idx += 256) s[SWK2 + idx] = wk2[idx];
    for (int idx = t; idx < 512;  idx += 256) s[SCM + idx] = g_cm[idx];
    if (t < 64)  s[SBR1 + t] = br1[t];
    if (t < 192) s[SWR2 + t] = wr2[t];
    if (t < 9)   s[SBK2 + t] = bk2[t];
    if (t < 3)   s[SBR2 + t] = br2[t];

    const int rowbase = (y0 >> 1) - 2;
    const int colbase = (x0 >> 1) - 2;
    for (int idx = t; idx < 35*64; idx += 256){
        int pix = idx >> 6, c = idx & 63;
        int wr = pix / 7, wc = pix % 7;
        int gy = refl(rowbase + wr), gx = refl(colbase + wc);
        s_f[c*35 + pix] = g_F[((b*HH + gy)*WW + gx)*CC + c];
    }
    __syncthreads();

    const int w = t >> 5, lane = t & 31;
    const int x = x0 + w;
    const int cx = max(0, (x - 1) >> 1);
    const int coloff = cx + 1 - (x0 >> 1);

    const float4* P4 = (const float4*)g_P;

    // ---- phase 1: logits / softmax / pooling for 4 queries ----
    for (int qi = 0; qi < 4; qi++){
        const int y = y0 + qi;
        const int cy = max(0, (y - 1) >> 1);
        const int par = ((y & 1) << 1) | (x & 1);
        const int rowoff = cy + 1 - (y0 >> 1);
        const int qbase = rowoff*7 + coloff;

        float4 pv  = P4[((b*HH + cy)*WW + cx)*(HID/4) + lane];
        float4 cmv = *(const float4*)&s[SCM + par*128 + lane*4];
        float h0 = gelu_fast(pv.x + cmv.x);
        float h1 = gelu_fast(pv.y + cmv.y);
        float h2 = gelu_fast(pv.z + cmv.z);
        float h3 = gelu_fast(pv.w + cmv.w);

        float lg[9];
        #pragma unroll
        for (int k = 0; k < 9; k++){
            float4 wv = *(const float4*)&s[SWK2 + k*128 + lane*4];
            float pr = wv.x*h0 + wv.y*h1 + wv.z*h2 + wv.w*h3;
            #pragma unroll
            for (int off = 16; off; off >>= 1) pr += __shfl_xor_sync(0xffffffffu, pr, off);
            lg[k] = pr + s[SBK2 + k];
        }

        float mx = lg[0];
        #pragma unroll
        for (int k = 1; k < 9; k++) mx = fmaxf(mx, lg[k]);
        float wk[9], ssum = 0.0f;
        #pragma unroll
        for (int k = 0; k < 9; k++){ wk[k] = __expf(lg[k] - mx); ssum += wk[k]; }
        float inv = __frcp_rn(ssum);
        #pragma unroll
        for (int k = 0; k < 9; k++) wk[k] *= inv;

        float fq0 = 0.0f, fq1 = 0.0f;
        #pragma unroll
        for (int k = 0; k < 9; k++){
            {
                int i = k*64 + lane;
                int ch = i / 9; int tap = i - 9*ch;
                int tap7 = tap + (tap/3)*4;
                fq0 += wk[k] * s_f[ch*35 + qbase + tap7];
            }
            {
                int i = k*64 + lane + 32;
                int ch = i / 9; int tap = i - 9*ch;
                int tap7 = tap + (tap/3)*4;
                fq1 += wk[k] * s_f[ch*35 + qbase + tap7];
            }
        }
        s[SFQ + w*256 + qi*64 + lane]      = fq0;
        s[SFQ + w*256 + qi*64 + lane + 32] = fq1;
    }
    __syncwarp();

    // ---- phase 2: 64x64 MLP for 4 queries at once (f32x2, j-paired) ----
    ull acc0[4], acc1[4];
    #pragma unroll
    for (int qi = 0; qi < 4; qi++){ acc0[qi] = 0ull; acc1[qi] = 0ull; }
    #pragma unroll 8
    for (int jp = 0; jp < 32; jp++){
        ull w0 = *(const ull*)&s[SW1 + lane*66 + 2*jp];
        ull w1 = *(const ull*)&s[SW1 + (lane+32)*66 + 2*jp];
        #pragma unroll
        for (int qi = 0; qi < 4; qi++){
            ull f = *(const ull*)&s[SFQ + w*256 + qi*64 + 2*jp];
            FMA2(acc0[qi], w0, f);
            FMA2(acc1[qi], w1, f);
        }
    }

    const float bias0 = s[SBR1 + lane], bias1 = s[SBR1 + lane + 32];
    #pragma unroll
    for (int qi = 0; qi < 4; qi++){
        const int y = y0 + qi;
        float l0, h0v, l1, h1v;
        UNPACK2(l0, h0v, acc0[qi]);
        UNPACK2(l1, h1v, acc1[qi]);
        float a0 = gelu_fast(l0 + h0v + bias0);
        float a1 = gelu_fast(l1 + h1v + bias1);
        #pragma unroll
        for (int r = 0; r < 3; r++){
            float pr = s[SWR2 + r*64 + lane] * a0 + s[SWR2 + r*64 + lane + 32] * a1;
            #pragma unroll
            for (int off = 16; off; off >>= 1) pr += __shfl_xor_sync(0xffffffffu, pr, off);
            if (lane == 0) out[((b*3 + r)*OH + y)*OW + x] = pr + s[SBR2 + r];
        }
    }
}

// ------------------------------------------------------------------------------
extern "C" void kernel_launch(void* const* d_in, const int* in_sizes, int n_in,
                              void* d_out, int out_size)
{
    const float* feat = (const float*)d_in[0];
    const float* w1m  = (const float*)d_in[1];
    const float* b1m  = (const float*)d_in[2];
    const float* w2m  = (const float*)d_in[3];
    const float* b2m  = (const float*)d_in[4];
    const float* wk1  = (const float*)d_in[5];
    const float* bk1  = (const float*)d_in[6];
    const float* wk2  = (const float*)d_in[7];
    const float* bk2  = (const float*)d_in[8];
    const float* wr1  = (const float*)d_in[9];
    const float* br1  = (const float*)d_in[10];
    const float* wr2  = (const float*)d_in[11];
    const float* br2  = (const float*)d_in[12];
    float* out = (float*)d_out;

    kernelT<<<1028, 256>>>(feat, w1m, b1m, w2m, b2m, wk1, bk1);
    dim3 gridB(2, 64, BB);
    kernelB<<<gridB, 256>>>(feat, wk1);
    dim3 gridC(32, 64, BB);
    kernelC<<<gridC, 256>>>(wk2, bk2, wr1, br1, wr2, br2, out);
}